// round 13
// baseline (speedup 1.0000x reference)
#include <cuda_runtime.h>
#include <cstdint>

#define MAX_NODES 100000
#define TB 512
#define DEG_SCALE 512.0f
#define INV_SCALE (1.0f / 512.0f)

// Packed accumulator: acc[i].x = 512*deg + C4, acc[i].y = S4.
// |C4| <= deg <= ~90 << 256, so deg and C4 separate exactly via rintf.
struct Scratch {
    float2   acc[MAX_NODES];
    unsigned done;            // last-block ticket
};
__device__ Scratch g_s;

__device__ __forceinline__ void red_v2(float2* addr, float a, float b) {
    asm volatile("red.global.add.v2.f32 [%0], {%1, %2};"
                 :: "l"(addr), "f"(a), "f"(b)
                 : "memory");
}

__global__ __launch_bounds__(TB, 3)
void fused_kernel(const float* __restrict__ pos,
                  const int*   __restrict__ ei,
                  int E, int N, float* __restrict__ out) {
    // ---- Phase 1: one edge per thread (work-stolen across many blocks) ----
    int e = blockIdx.x * TB + threadIdx.x;
    if (e < E) {
        int s = ei[e];
        int t = ei[E + e];
        float2 ps = __ldg((const float2*)pos + s);
        float2 pt = __ldg((const float2*)pos + t);
        float dx = pt.x - ps.x;
        float dy = pt.y - ps.y;
        float nrm = sqrtf(fmaf(dx, dx, dy * dy));
        float inv = 1.0f / fmaxf(nrm, 1e-8f);
        float u = dx * inv, v = dy * inv;
        // cos(2t) = u^2 - v^2 ; sin(2t) = 2uv ; double-angle again for 4t.
        float a = u * u - v * v;
        float b = 2.0f * u * v;
        float c4 = a * a - b * b;
        float s4 = 2.0f * a * b;
        // 4-theta invariant under d -> -d: identical payload to both endpoints.
        // Degree folded into the x channel as +DEG_SCALE.
        red_v2(&g_s.acc[s], DEG_SCALE + c4, s4);
        red_v2(&g_s.acc[t], DEG_SCALE + c4, s4);
    }

    // ---- Last-block handoff (threadFenceReduction pattern) ----
    __threadfence();                   // publish this thread's REDs device-wide
    __syncthreads();
    __shared__ bool s_last;
    if (threadIdx.x == 0) {
        unsigned tkt = atomicAdd(&g_s.done, 1u);
        s_last = (tkt == gridDim.x - 1);
    }
    __syncthreads();
    if (!s_last) return;

    // ---- Phase 2 (last block only): node reduction over all N ----
    __threadfence();                   // acquire: all blocks' REDs visible
    float pl = 0.0f, np = 0.0f;
    #pragma unroll 8
    for (int i = threadIdx.x; i < N; i += TB) {
        float2 acc = g_s.acc[i];
        float k  = rintf(acc.x * INV_SCALE);       // exact degree
        float c4 = fmaf(k, -DEG_SCALE, acc.x);     // C4 = x - 512*k
        float s4 = acc.y;
        // sum_{i<j}(dot^2 - dot^4) = (k^2 - C4^2 - S4^2)/16 (incl. 0.5 pair factor)
        pl += (k * k - (c4 * c4 + s4 * s4)) * 0.0625f;
        np += 0.5f * k * (k - 1.0f);
    }

    #pragma unroll
    for (int o = 16; o > 0; o >>= 1) {
        pl += __shfl_down_sync(0xffffffffu, pl, o);
        np += __shfl_down_sync(0xffffffffu, np, o);
    }
    __shared__ float s_pl[TB / 32];
    __shared__ float s_np[TB / 32];
    int lane = threadIdx.x & 31;
    int wid  = threadIdx.x >> 5;
    if (lane == 0) { s_pl[wid] = pl; s_np[wid] = np; }
    __syncthreads();
    if (wid == 0) {
        pl = (lane < TB / 32) ? s_pl[lane] : 0.0f;
        np = (lane < TB / 32) ? s_np[lane] : 0.0f;
        #pragma unroll
        for (int o = 16; o > 0; o >>= 1) {
            pl += __shfl_down_sync(0xffffffffu, pl, o);
            np += __shfl_down_sync(0xffffffffu, np, o);
        }
        if (lane == 0) out[0] = pl / fmaxf(np, 1.0f);
    }
}

extern "C" void kernel_launch(void* const* d_in, const int* in_sizes, int n_in,
                              void* d_out, int out_size) {
    const float* pos = (const float*)d_in[0];
    const int*   ei  = (const int*)d_in[2];
    int N = in_sizes[0] / 2;      // node_positions: (1, N, 2)
    int E = in_sizes[2] / 2;      // edge_index: (2, E)

    static bool configured = false;
    if (!configured) {
        cudaFuncSetAttribute(fused_kernel,
                             cudaFuncAttributePreferredSharedMemoryCarveout, 0);
        configured = true;
    }

    void* scratch_ptr = nullptr;
    cudaGetSymbolAddress(&scratch_ptr, g_s);
    cudaMemsetAsync(scratch_ptr, 0, sizeof(Scratch));  // captured memset node

    int grid = (E + TB - 1) / TB;
    fused_kernel<<<grid, TB>>>(pos, ei, E, N, (float*)d_out);
}

// round 14
// speedup vs baseline: 1.4286x; 1.4286x over previous
#include <cuda_runtime.h>
#include <cstdint>

#define MAX_NODES 100000
#define NODE_TB   1024
#define NODE_GRID 148   // 148*1024 = 151552 >= 100000, single wave, 1 node/thread
#define DEG_SCALE 512.0f
#define INV_SCALE (1.0f / 512.0f)

// Packed accumulator: acc[i].x = 512*deg + C4, acc[i].y = S4.
// |C4| <= deg <= ~90 << 256, so deg and C4 separate exactly via rintf.
// Zero-initialized at module load; node_kernel self-cleans every word it
// consumes, so no memset node is needed and the graph has only 2 nodes.
struct Scratch {
    float2   acc[MAX_NODES];
    float    part[2];         // [0] pair_loss_sum, [1] n_pairs
    unsigned done;
};
__device__ Scratch g_s;

__device__ __forceinline__ void red_v2(float2* addr, float a, float b) {
    asm volatile("red.global.add.v2.f32 [%0], {%1, %2};"
                 :: "l"(addr), "f"(a), "f"(b)
                 : "memory");
}

__global__ void edge_kernel(const float* __restrict__ pos,
                            const int*   __restrict__ ei,
                            int E) {
    int e = blockIdx.x * blockDim.x + threadIdx.x;
    if (e >= E) return;
    int s = ei[e];
    int t = ei[E + e];
    float2 ps = __ldg((const float2*)pos + s);
    float2 pt = __ldg((const float2*)pos + t);
    float dx = pt.x - ps.x;
    float dy = pt.y - ps.y;
    float nrm = sqrtf(fmaf(dx, dx, dy * dy));
    float inv = 1.0f / fmaxf(nrm, 1e-8f);
    float u = dx * inv, v = dy * inv;
    // cos(2t) = u^2 - v^2 ; sin(2t) = 2uv ; double-angle again for 4t.
    float a = u * u - v * v;
    float b = 2.0f * u * v;
    float c4 = a * a - b * b;
    float s4 = 2.0f * a * b;
    // 4-theta terms invariant under d -> -d: identical payload to both endpoints.
    // Degree folded into the x channel as +DEG_SCALE.
    red_v2(&g_s.acc[s], DEG_SCALE + c4, s4);
    red_v2(&g_s.acc[t], DEG_SCALE + c4, s4);
}

__global__ __launch_bounds__(NODE_TB, 1)
void node_kernel(int n, float* __restrict__ out) {
    const int i = blockIdx.x * blockDim.x + threadIdx.x;

    float pl = 0.0f, np = 0.0f;
    if (i < n) {
        float2 acc = g_s.acc[i];
        g_s.acc[i] = make_float2(0.f, 0.f);        // self-clean for next replay
        float k  = rintf(acc.x * INV_SCALE);       // exact degree
        float c4 = fmaf(k, -DEG_SCALE, acc.x);     // C4 = x - 512*k
        float s4 = acc.y;
        // sum_{i<j}(dot^2 - dot^4) = (k^2 - C4^2 - S4^2)/16 (incl. 0.5 pair factor)
        pl = (k * k - (c4 * c4 + s4 * s4)) * 0.0625f;
        np = 0.5f * k * (k - 1.0f);
    }

    #pragma unroll
    for (int o = 16; o > 0; o >>= 1) {
        pl += __shfl_down_sync(0xffffffffu, pl, o);
        np += __shfl_down_sync(0xffffffffu, np, o);
    }
    __shared__ float s_pl[32];
    __shared__ float s_np[32];
    int lane = threadIdx.x & 31;
    int wid  = threadIdx.x >> 5;
    if (lane == 0) { s_pl[wid] = pl; s_np[wid] = np; }
    __syncthreads();
    if (wid == 0) {
        pl = s_pl[lane];
        np = s_np[lane];
        #pragma unroll
        for (int o = 16; o > 0; o >>= 1) {
            pl += __shfl_down_sync(0xffffffffu, pl, o);
            np += __shfl_down_sync(0xffffffffu, np, o);
        }
        if (lane == 0) {
            atomicAdd(&g_s.part[0], pl);
            atomicAdd(&g_s.part[1], np);
            __threadfence();
            unsigned done = atomicAdd(&g_s.done, 1u);
            if (done == gridDim.x - 1) {
                volatile float* p = g_s.part;
                float a = p[0];
                float b = p[1];
                out[0] = a / fmaxf(b, 1.0f);
                // last block: reset scalars for the next replay
                g_s.part[0] = 0.f;
                g_s.part[1] = 0.f;
                g_s.done = 0u;
            }
        }
    }
}

extern "C" void kernel_launch(void* const* d_in, const int* in_sizes, int n_in,
                              void* d_out, int out_size) {
    const float* pos = (const float*)d_in[0];
    const int*   ei  = (const int*)d_in[2];
    int N = in_sizes[0] / 2;      // node_positions: (1, N, 2)
    int E = in_sizes[2] / 2;      // edge_index: (2, E)

    static bool configured = false;
    if (!configured) {
        cudaFuncSetAttribute(edge_kernel,
                             cudaFuncAttributePreferredSharedMemoryCarveout, 0);
        configured = true;
    }

    const int TB = 256;
    edge_kernel<<<(E + TB - 1) / TB, TB>>>(pos, ei, E);
    node_kernel<<<NODE_GRID, NODE_TB>>>(N, (float*)d_out);
}